// round 8
// baseline (speedup 1.0000x reference)
#include <cuda_runtime.h>
#include <cuda_bf16.h>
#include <cstdint>

#define CC 512
#define TT 8192
#define BBATCH 16
#define SEGS 16
#define SEG_T 512                 // t per segment
#define NCTA (BBATCH * SEGS)      // 256
#define NTHREADS 256
#define DIVC 512.0f
#define EPSV 1e-8f
#define FULL 0xffffffffu

// one 16B record per segment: {s_total, q_total, flag, pad}; flag 0=empty, 1=published
__device__ float4 g_rec[NCTA];

__global__ void init_rec_kernel() {
    int i = blockIdx.x * blockDim.x + threadIdx.x;
    if (i < NCTA) g_rec[i] = make_float4(0.f, 0.f, 0.f, 0.f);
}

__device__ __forceinline__ float4 ld_rec_vol(const float4* p) {
    float4 r;
    asm volatile("ld.volatile.global.v4.f32 {%0,%1,%2,%3}, [%4];"
                 : "=f"(r.x), "=f"(r.y), "=f"(r.z), "=f"(r.w) : "l"(p));
    return r;
}
__device__ __forceinline__ void st_rec_vol(float4* p, float s, float q, int flag) {
    asm volatile("st.volatile.global.v4.f32 [%0], {%1,%2,%3,%4};"
                 :: "l"(p), "f"(s), "f"(q), "f"(__int_as_float(flag)), "f"(0.f)
                 : "memory");
}

__global__ void __launch_bounds__(NTHREADS, 2)
newNormal_kernel(const float* __restrict__ x,
                 const float* __restrict__ gains,
                 const float* __restrict__ bias,
                 float* __restrict__ out) {
    __shared__ float4 parts[2][8][128];          // [s|q][warp][t_float4]  32 KB
    __shared__ float st[SEG_T], qt[SEG_T];
    __shared__ float meanv[SEG_T], invv[SEG_T];
    __shared__ float exsq[2];

    const int bid  = blockIdx.x;
    const int b    = bid >> 4;
    const int seg  = bid & 15;
    const int t0   = seg * SEG_T;
    const int tid  = threadIdx.x;
    const int lane = tid & 31;
    const int w    = tid >> 5;    // 8 warps
    const int tg   = tid & 3;     // t-float4 phase
    const int j    = tid >> 2;    // 0..63, channels c = j + 64k

    const float* xb = x + ((size_t)(b * CC + j)) * TT + t0;

    float gn[8], bsv[8];
#pragma unroll
    for (int k = 0; k < 8; k++) {
        gn[k]  = __ldg(gains + j + 64 * k);
        bsv[k] = __ldg(bias  + j + 64 * k);
    }

    // ================= Pass 1: per-t channel sums (pure streaming) =================
#pragma unroll 2
    for (int m = 0; m < 32; m++) {
        const float* px = xb + 4 * (tg + 4 * m);
        float4 s4 = make_float4(0.f,0.f,0.f,0.f), q4 = make_float4(0.f,0.f,0.f,0.f);
#pragma unroll
        for (int k = 0; k < 8; k++) {
            float4 v = __ldg((const float4*)(px + (size_t)(64 * k) * TT));
            s4.x += v.x; s4.y += v.y; s4.z += v.z; s4.w += v.w;
            q4.x = fmaf(v.x, v.x, q4.x); q4.y = fmaf(v.y, v.y, q4.y);
            q4.z = fmaf(v.z, v.z, q4.z); q4.w = fmaf(v.w, v.w, q4.w);
        }
        // reduce over the 8 channel-groups within the warp (lanes differing in bits 2..4)
#pragma unroll
        for (int d = 16; d >= 4; d >>= 1) {
            s4.x += __shfl_down_sync(FULL, s4.x, d); s4.y += __shfl_down_sync(FULL, s4.y, d);
            s4.z += __shfl_down_sync(FULL, s4.z, d); s4.w += __shfl_down_sync(FULL, s4.w, d);
            q4.x += __shfl_down_sync(FULL, q4.x, d); q4.y += __shfl_down_sync(FULL, q4.y, d);
            q4.z += __shfl_down_sync(FULL, q4.z, d); q4.w += __shfl_down_sync(FULL, q4.w, d);
        }
        if (lane < 4) {
            parts[0][w][m * 4 + lane] = s4;     // t_float4 index = tg + 4m = lane + 4m
            parts[1][w][m * 4 + lane] = q4;
        }
    }
    __syncthreads();

    // cross-warp reduce: 128 threads for s, 128 for q
    {
        const int sq = tid >> 7;
        const int i  = tid & 127;
        float4 acc = make_float4(0.f,0.f,0.f,0.f);
#pragma unroll
        for (int w2 = 0; w2 < 8; w2++) {
            float4 a = parts[sq][w2][i];
            acc.x += a.x; acc.y += a.y; acc.z += a.z; acc.w += a.w;
        }
        float* dst = sq ? qt : st;
        *(float4*)&dst[4 * i] = acc;
    }
    __syncthreads();

    // ============ warp 0: scan 512, publish totals, one shallow look-back ============
    if (w == 0) {
        const int base = 16 * lane;
        float s = 0.f, q = 0.f;
#pragma unroll
        for (int i = 0; i < 16; i++) {
            s += st[base + i]; st[base + i] = s;
            q += qt[base + i]; qt[base + i] = q;
        }
        float is = s, iq = q;
#pragma unroll
        for (int d = 1; d < 32; d <<= 1) {
            float a = __shfl_up_sync(FULL, is, d);
            float c = __shfl_up_sync(FULL, iq, d);
            if (lane >= d) { is += a; iq += c; }
        }
        const float off_s = is - s, off_q = iq - q;   // exclusive lane offsets
#pragma unroll
        for (int i = 0; i < 16; i++) {
            st[base + i] += off_s;
            qt[base + i] += off_q;
        }
        const float tot_s = __shfl_sync(FULL, is, 31);
        const float tot_q = __shfl_sync(FULL, iq, 31);

        if (lane == 0) st_rec_vol(&g_rec[bid], tot_s, tot_q, 1);

        float ex_s = 0.f, ex_q = 0.f;
        if (seg > 0) {
            const int p = bid - 1 - lane;
            const bool valid = lane < seg;            // depth <= 15 -> one round
            float rs = 0.f, rq = 0.f;
            for (;;) {
                int f = 1;
                if (valid) {
                    float4 r = ld_rec_vol(&g_rec[p]);
                    rs = r.x; rq = r.y; f = __float_as_int(r.z);
                }
                if (!__ballot_sync(FULL, f == 0)) break;
                __nanosleep(40);
            }
            float cs = valid ? rs : 0.f, cq = valid ? rq : 0.f;
#pragma unroll
            for (int d = 16; d; d >>= 1) {
                cs += __shfl_down_sync(FULL, cs, d);
                cq += __shfl_down_sync(FULL, cq, d);
            }
            ex_s = __shfl_sync(FULL, cs, 0);
            ex_q = __shfl_sync(FULL, cq, 0);
        }
        if (lane == 0) { exsq[0] = ex_s; exsq[1] = ex_q; }
    }
    __syncthreads();

    // ---- mean / inv for all 512 t ----
    {
        const float exs = exsq[0], exq = exsq[1];
#pragma unroll
        for (int r2 = 0; r2 < 2; r2++) {
            const int t = tid + 256 * r2;
            const float cs = exs + st[t];
            const float cq = exq + qt[t];
            const float dv = 1.0f / ((float)(t0 + t + 1) * DIVC);
            const float m  = cs * dv;
            const float var = fmaf(-m, m, cq * dv);
            meanv[t] = m;
            invv[t]  = rsqrtf(var + EPSV);
        }
    }
    __syncthreads();

    // ============== Pass 2: reverse-order re-read (L2 tail hits) + write ==============
    float* ob = out + ((size_t)(b * CC + j)) * TT + t0;
#pragma unroll 2
    for (int m = 31; m >= 0; m--) {
        const int tf = 4 * (tg + 4 * m);
        const float4 m4 = *(const float4*)&meanv[tf];
        const float4 i4 = *(const float4*)&invv[tf];
#pragma unroll
        for (int k = 0; k < 8; k++) {
            float4 v = __ldcs((const float4*)(xb + tf + (size_t)(64 * k) * TT));
            float4 o;
            o.x = fmaf((v.x - m4.x) * i4.x, gn[k], bsv[k]);
            o.y = fmaf((v.y - m4.y) * i4.y, gn[k], bsv[k]);
            o.z = fmaf((v.z - m4.z) * i4.z, gn[k], bsv[k]);
            o.w = fmaf((v.w - m4.w) * i4.w, gn[k], bsv[k]);
            __stcs((float4*)(ob + tf + (size_t)(64 * k) * TT), o);
        }
    }
}

extern "C" void kernel_launch(void* const* d_in, const int* in_sizes, int n_in,
                              void* d_out, int out_size) {
    (void)in_sizes; (void)n_in; (void)out_size;
    const float* x     = (const float*)d_in[0];
    const float* gains = (const float*)d_in[1];
    const float* bias  = (const float*)d_in[2];
    float* out = (float*)d_out;

    init_rec_kernel<<<1, NCTA>>>();
    newNormal_kernel<<<NCTA, NTHREADS>>>(x, gains, bias, out);
}

// round 10
// speedup vs baseline: 2.0998x; 2.0998x over previous
#include <cuda_runtime.h>
#include <cuda_bf16.h>
#include <cstdint>

#define CC 512
#define TT 8192
#define SEG_T 64
#define SEGS 128                 // TT / SEG_T
#define NCTA 2048                // 16 batch * 128 segs
#define NTHREADS 512
#define DIVC 512.0f
#define EPSV 1e-8f
#define FULL 0xffffffffu

// one 16B record per segment: {s, q, flag, pad}; flag 0=empty, 1=aggregate, 2=prefix
__device__ float4 g_rec[NCTA];

__global__ void init_rec_kernel() {
    int i = blockIdx.x * blockDim.x + threadIdx.x;
    if (i < NCTA) g_rec[i] = make_float4(0.f, 0.f, 0.f, 0.f);
}

__device__ __forceinline__ float4 ld_rec_vol(const float4* p) {
    float4 r;
    asm volatile("ld.volatile.global.v4.f32 {%0,%1,%2,%3}, [%4];"
                 : "=f"(r.x), "=f"(r.y), "=f"(r.z), "=f"(r.w) : "l"(p));
    return r;
}
__device__ __forceinline__ void st_rec_vol(float4* p, float s, float q, int flag) {
    asm volatile("st.volatile.global.v4.f32 [%0], {%1,%2,%3,%4};"
                 :: "l"(p), "f"(s), "f"(q), "f"(__int_as_float(flag)), "f"(0.f)
                 : "memory");
}

__global__ void __launch_bounds__(NTHREADS, 2)
newNormal_kernel(const float* __restrict__ x,
                 const float* __restrict__ gains,
                 const float* __restrict__ bias,
                 float* __restrict__ out) {
    __shared__ float4 ps[32][16];        // [row][t-chunk] sum partials   8 KB
    __shared__ float4 pq[32][16];        //                sq partials    8 KB
    __shared__ float4 psr[4][16];        // compacted partials (race-free)
    __shared__ float4 pqr[4][16];
    __shared__ float4 mean4[16], inv4[16];

    const int bid  = blockIdx.x;
    const int b    = bid >> 7;           // batch
    const int seg  = bid & 127;          // segment within row (ascending bid)
    const int t0   = seg * SEG_T;
    const int tid  = threadIdx.x;
    const int lane = tid & 31;
    const int chunk = tid & 15;          // fixed 4-t chunk for this thread
    const int r     = tid >> 4;          // 0..31: channel phase

    const float* xb = x + ((size_t)b * CC) * TT + t0 + 4 * chunk;

    // ======== Pass 1: warp-contiguous streaming read + per-chunk sums ========
    float4 s4 = make_float4(0.f, 0.f, 0.f, 0.f);
    float4 q4 = make_float4(0.f, 0.f, 0.f, 0.f);
#pragma unroll
    for (int iblk = 0; iblk < 2; iblk++) {
        float4 v[8];
#pragma unroll
        for (int u = 0; u < 8; u++) {
            const int c = (iblk * 8 + u) * 32 + r;        // channel
            v[u] = __ldg((const float4*)(xb + (size_t)c * TT));
        }
#pragma unroll
        for (int u = 0; u < 8; u++) {
            float4 t = v[u];
            s4.x += t.x; s4.y += t.y; s4.z += t.z; s4.w += t.w;
            q4.x = fmaf(t.x, t.x, q4.x); q4.y = fmaf(t.y, t.y, q4.y);
            q4.z = fmaf(t.z, t.z, q4.z); q4.w = fmaf(t.w, t.w, q4.w);
        }
    }
    ps[r][chunk] = s4;
    pq[r][chunk] = q4;
    __syncthreads();

    // ======== partial cross-thread reduce: 128 threads, 8 rows each ========
    if (tid < 128) {
        const int which = tid >> 6;                 // 0 = s, 1 = q
        const int idx   = tid & 63;
        const int ch    = idx & 15;
        const int quad  = idx >> 4;                 // 0..3
        float4 acc = make_float4(0.f, 0.f, 0.f, 0.f);
        float4 (*src)[16] = which ? pq : ps;
#pragma unroll
        for (int rr = 0; rr < 8; rr++) {
            float4 a = src[quad * 8 + rr][ch];
            acc.x += a.x; acc.y += a.y; acc.z += a.z; acc.w += a.w;
        }
        float4 (*dst)[16] = which ? pqr : psr;      // separate arrays: no race
        dst[quad][ch] = acc;
    }
    __syncthreads();

    // ======== warp 0: final reduce + scan 64 + shallow look-back ========
    if (tid < 32) {
        float4 sv = make_float4(0.f,0.f,0.f,0.f), qv = make_float4(0.f,0.f,0.f,0.f);
        if (lane < 16) {
#pragma unroll
            for (int quad = 0; quad < 4; quad++) {
                float4 a = psr[quad][lane];
                sv.x += a.x; sv.y += a.y; sv.z += a.z; sv.w += a.w;
                float4 c = pqr[quad][lane];
                qv.x += c.x; qv.y += c.y; qv.z += c.z; qv.w += c.w;
            }
        }
        // inclusive scan within the 4-t chunk
        float4 is, iq;
        is.x = sv.x; is.y = is.x + sv.y; is.z = is.y + sv.z; is.w = is.z + sv.w;
        iq.x = qv.x; iq.y = iq.x + qv.y; iq.z = iq.y + qv.z; iq.w = iq.z + qv.w;
        // scan chunk totals across lanes 0..15
        const float gs = is.w, gq = iq.w;
        float ssc = gs, qsc = gq;
#pragma unroll
        for (int d = 1; d < 16; d <<= 1) {
            float a = __shfl_up_sync(FULL, ssc, d);
            float c = __shfl_up_sync(FULL, qsc, d);
            if (lane >= d && lane < 16) { ssc += a; qsc += c; }
        }
        const float exg_s = ssc - gs, exg_q = qsc - gq;
        const float tot_s = __shfl_sync(FULL, ssc, 15);
        const float tot_q = __shfl_sync(FULL, qsc, 15);

        // decoupled look-back, depth <= 127 (warp-parallel, 32 records/round)
        float ex_s = 0.f, ex_q = 0.f;
        if (seg == 0) {
            if (lane == 0) st_rec_vol(&g_rec[bid], tot_s, tot_q, 2);
        } else {
            if (lane == 0) st_rec_vol(&g_rec[bid], tot_s, tot_q, 1);
            const int base = bid - seg;
            int p_hi = bid - 1;
            for (;;) {
                const int p = p_hi - lane;
                float rs, rq; int f;
                if (p >= base) {
                    float4 rr2 = ld_rec_vol(&g_rec[p]);
                    rs = rr2.x; rq = rr2.y; f = __float_as_int(rr2.z);
                } else { rs = 0.f; rq = 0.f; f = 2; }
                if (__ballot_sync(FULL, f == 0)) { __nanosleep(32); continue; }
                const unsigned m2 = __ballot_sync(FULL, f == 2);
                float cs, cq;
                if (m2) {
                    const int l2 = __ffs(m2) - 1;
                    cs = (lane <= l2) ? rs : 0.f;
                    cq = (lane <= l2) ? rq : 0.f;
                } else { cs = rs; cq = rq; }
#pragma unroll
                for (int d = 16; d; d >>= 1) {
                    cs += __shfl_down_sync(FULL, cs, d);
                    cq += __shfl_down_sync(FULL, cq, d);
                }
                ex_s += __shfl_sync(FULL, cs, 0);
                ex_q += __shfl_sync(FULL, cq, 0);
                if (m2) break;
                p_hi -= 32;
            }
            if (lane == 0) st_rec_vol(&g_rec[bid], ex_s + tot_s, ex_q + tot_q, 2);
        }

        // mean / rsqrt per t chunk
        if (lane < 16) {
            const float bs = ex_s + exg_s;
            const float bq = ex_q + exg_q;
            const int tb = t0 + 4 * lane;
            float4 m4, i4;
            {
                float dv = 1.0f / ((float)(tb + 1) * DIVC);
                float m = (bs + is.x) * dv;
                float var = fmaf(-m, m, (bq + iq.x) * dv);
                m4.x = m; i4.x = rsqrtf(var + EPSV);
            }
            {
                float dv = 1.0f / ((float)(tb + 2) * DIVC);
                float m = (bs + is.y) * dv;
                float var = fmaf(-m, m, (bq + iq.y) * dv);
                m4.y = m; i4.y = rsqrtf(var + EPSV);
            }
            {
                float dv = 1.0f / ((float)(tb + 3) * DIVC);
                float m = (bs + is.z) * dv;
                float var = fmaf(-m, m, (bq + iq.z) * dv);
                m4.z = m; i4.z = rsqrtf(var + EPSV);
            }
            {
                float dv = 1.0f / ((float)(tb + 4) * DIVC);
                float m = (bs + is.w) * dv;
                float var = fmaf(-m, m, (bq + iq.w) * dv);
                m4.w = m; i4.w = rsqrtf(var + EPSV);
            }
            mean4[lane] = m4;
            inv4[lane]  = i4;
        }
    }
    __syncthreads();

    // ======== Pass 2: re-read own 128KB (L2-hot), normalize, write ========
    {
        const float4 m4 = mean4[chunk];
        const float4 i4 = inv4[chunk];
        float* ob = out + ((size_t)b * CC) * TT + t0 + 4 * chunk;
#pragma unroll
        for (int iblk = 0; iblk < 2; iblk++) {
            float4 v[8];
            float gg[8], bb[8];
#pragma unroll
            for (int u = 0; u < 8; u++) {
                const int c = (iblk * 8 + u) * 32 + r;
                v[u]  = __ldg((const float4*)(xb + (size_t)c * TT));
                gg[u] = __ldg(gains + c);
                bb[u] = __ldg(bias  + c);
            }
#pragma unroll
            for (int u = 0; u < 8; u++) {
                const int c = (iblk * 8 + u) * 32 + r;
                float4 t = v[u];
                float4 o;
                o.x = fmaf((t.x - m4.x) * i4.x, gg[u], bb[u]);
                o.y = fmaf((t.y - m4.y) * i4.y, gg[u], bb[u]);
                o.z = fmaf((t.z - m4.z) * i4.z, gg[u], bb[u]);
                o.w = fmaf((t.w - m4.w) * i4.w, gg[u], bb[u]);
                __stcs((float4*)(ob + (size_t)c * TT), o);
            }
        }
    }
}

extern "C" void kernel_launch(void* const* d_in, const int* in_sizes, int n_in,
                              void* d_out, int out_size) {
    (void)in_sizes; (void)n_in; (void)out_size;
    const float* x     = (const float*)d_in[0];
    const float* gains = (const float*)d_in[1];
    const float* bias  = (const float*)d_in[2];
    float* out = (float*)d_out;

    init_rec_kernel<<<NCTA / 256, 256>>>();
    newNormal_kernel<<<NCTA, NTHREADS>>>(x, gains, bias, out);
}